// round 10
// baseline (speedup 1.0000x reference)
#include <cuda_runtime.h>
#include <cuda_fp16.h>
#include <cstdint>
#include <math.h>

// ---------------------------------------------------------------------------
// PointPillars BEV extractor.
//  mma layers: fp16 m16n8k16 (11-bit mantissa == tf32 staging), fp32 accum.
//  A fragments via ldmatrix.x4; B pair-packed for LDS.128; half activations.
//  Output: (2, 84, 496, 432) f32 = concat(x1[4], x2[16], x3[64])
// ---------------------------------------------------------------------------

namespace {
constexpr int Hh  = 496;
constexpr int Ww  = 432;
constexpr int HWc = Hh * Ww;
constexpr int Bc  = 2;
constexpr int XO     = 112;     // output px per x-block
constexpr int SLABPX = 116;     // staged input px per row-slab
}

// D += A(16x16) * B(16x8), fp16 inputs, fp32 accum.
__device__ __forceinline__ void mma16(float* d,
                                      uint32_t a0, uint32_t a1, uint32_t a2, uint32_t a3,
                                      uint32_t b0, uint32_t b1) {
    asm("mma.sync.aligned.m16n8k16.row.col.f32.f16.f16.f32 "
        "{%0,%1,%2,%3},{%4,%5,%6,%7},{%8,%9},{%0,%1,%2,%3};"
        : "+f"(d[0]), "+f"(d[1]), "+f"(d[2]), "+f"(d[3])
        : "r"(a0), "r"(a1), "r"(a2), "r"(a3), "r"(b0), "r"(b1));
}

__device__ __forceinline__ void ldmA(uint32_t* r, uint32_t saddr) {
    asm volatile("ldmatrix.sync.aligned.m8n8.x4.shared.b16 {%0,%1,%2,%3}, [%4];"
        : "=r"(r[0]), "=r"(r[1]), "=r"(r[2]), "=r"(r[3]) : "r"(saddr));
}

// Scratch (allocation-free rule)
__device__ float  g_bufA[(size_t)Bc * 64 * HWc];   // fp32 canvas / half ping-pong
__device__ float  g_bufB[(size_t)Bc * 64 * HWc];
__device__ int    g_count[Bc * HWc];
__device__ float  g_sum[(size_t)Bc * HWc * 3];
__device__ __half g_wpack[214272];                  // packed weights (half)

namespace {
constexpr int WO_B1C0 = 0;         // 64->16(pad from 4), 9216
constexpr int WO_B2   = 9216;      // 5 x 2304
constexpr int WO_B3C0 = 20736;     // 16->64, 9216
constexpr int WO_B3   = 29952;     // 5 x 36864
}

// ---------------------------------------------------------------------------
__global__ void zero_kernel() {
    const size_t stride = (size_t)gridDim.x * blockDim.x;
    size_t i = (size_t)blockIdx.x * blockDim.x + threadIdx.x;
    const float4 z4 = make_float4(0.f, 0.f, 0.f, 0.f);
    const int4   zi = make_int4(0, 0, 0, 0);
    const size_t nA = (size_t)Bc * 64 * HWc / 4;
    for (size_t j = i; j < nA; j += stride) reinterpret_cast<float4*>(g_bufA)[j] = z4;
    const size_t nC = (size_t)Bc * HWc / 4;
    for (size_t j = i; j < nC; j += stride) reinterpret_cast<int4*>(g_count)[j] = zi;
    const size_t nS = (size_t)Bc * HWc * 3 / 4;
    for (size_t j = i; j < nS; j += stride) reinterpret_cast<float4*>(g_sum)[j] = z4;
}

__device__ __forceinline__ void point_cell(float px, float py, int& ix, int& iy) {
    float fx = __fmul_rn(px, 6.25f);
    float fy = __fmul_rn(__fadd_rn(py, 39.68f), 6.25f);
    ix = min(max((int)floorf(fx), 0), Ww - 1);
    iy = min(max((int)floorf(fy), 0), Hh - 1);
}

__global__ void count_kernel(const float* __restrict__ pts, int npts, int nper) {
    int i = blockIdx.x * blockDim.x + threadIdx.x;
    if (i >= npts) return;
    float4 p = reinterpret_cast<const float4*>(pts)[i];
    int b = i / nper;
    int ix, iy; point_cell(p.x, p.y, ix, iy);
    int cell = b * HWc + iy * Ww + ix;
    atomicAdd(&g_count[cell], 1);
    atomicAdd(&g_sum[(size_t)cell * 3 + 0], p.x);
    atomicAdd(&g_sum[(size_t)cell * 3 + 1], p.y);
    atomicAdd(&g_sum[(size_t)cell * 3 + 2], p.z);
}

// VFE -> NHWC fp32 canvas.
__global__ void vfe_kernel(const float* __restrict__ pts,
                           const float* __restrict__ w,
                           const float* __restrict__ s,
                           const float* __restrict__ t,
                           int npts, int nper) {
    __shared__ float sw[640];
    __shared__ float ss[64];
    __shared__ float st[64];
    for (int j = threadIdx.x; j < 640; j += blockDim.x) sw[j] = w[j];
    if (threadIdx.x < 64) { ss[threadIdx.x] = s[threadIdx.x]; st[threadIdx.x] = t[threadIdx.x]; }
    __syncthreads();

    int i = blockIdx.x * blockDim.x + threadIdx.x;
    if (i >= npts) return;
    float4 p = reinterpret_cast<const float4*>(pts)[i];
    int b = i / nper;
    int ix, iy; point_cell(p.x, p.y, ix, iy);
    int cell = b * HWc + iy * Ww + ix;

    float n  = (float)g_count[cell];
    float mx = __fdiv_rn(g_sum[(size_t)cell * 3 + 0], n);
    float my = __fdiv_rn(g_sum[(size_t)cell * 3 + 1], n);
    float mz = __fdiv_rn(g_sum[(size_t)cell * 3 + 2], n);

    float cx = __fadd_rn(__fmul_rn((float)ix, 0.16f), 0.08f);
    float cy = __fadd_rn(__fmul_rn((float)iy, 0.16f), __fadd_rn(0.08f, -39.68f));
    float cz = -1.0f;

    float f[10];
    f[0] = p.x; f[1] = p.y; f[2] = p.z; f[3] = p.w;
    f[4] = __fadd_rn(p.x, -mx); f[5] = __fadd_rn(p.y, -my); f[6] = __fadd_rn(p.z, -mz);
    f[7] = __fadd_rn(p.x, -cx); f[8] = __fadd_rn(p.y, -cy); f[9] = __fadd_rn(p.z, -cz);

    int* canvas = reinterpret_cast<int*>(g_bufA);
    size_t base = (size_t)cell * 64;
    #pragma unroll 4
    for (int c = 0; c < 64; c++) {
        float d = 0.f;
        #pragma unroll
        for (int j = 0; j < 10; j++) d = fmaf(sw[c * 10 + j], f[j], d);
        float v = fmaxf(fmaf(d, ss[c], st[c]), 0.f);
        v = fmaxf(v, fmaxf(st[c], 0.f));
        atomicMax(&canvas[base + c], __float_as_int(v));
    }
}

// ---------------------------------------------------------------------------
// Fused weight pre-pack: mma layers -> g_wpack, pair-packed k16 fragments.
//  Pair block (t=ky*3+kx, chunk16, n16pair) = 256 halves (512B); per lane a
//  uint4 = [b0,b1 of even n8 | b0,b1 of odd n8].
// ---------------------------------------------------------------------------
struct PackArgs { const float* b1w0; const float* b2w; const float* b3w0; const float* b3w; };

__global__ void pack_all(PackArgs pa) {
    int seg = blockIdx.y;
    int i = blockIdx.x * 256 + threadIdx.x;
    int CIN, COUTp, COUTr, off;
    const float* src;
    if (seg == 0)      { CIN = 64; COUTp = 16; COUTr = 4;  src = pa.b1w0;                   off = WO_B1C0; }
    else if (seg <= 5) { CIN = 16; COUTp = 16; COUTr = 16; src = pa.b2w + (seg - 1) * 2304; off = WO_B2 + (seg - 1) * 2304; }
    else if (seg == 6) { CIN = 16; COUTp = 64; COUTr = 64; src = pa.b3w0;                   off = WO_B3C0; }
    else               { CIN = 64; COUTp = 64; COUTr = 64; src = pa.b3w + (seg - 7) * 36864; off = WO_B3 + (seg - 7) * 36864; }
    int total = COUTp * CIN * 9;
    if (i >= total) return;
    int oc  = i / (CIN * 9);
    int rem = i - oc * (CIN * 9);
    int ic  = rem / 9;
    int k   = rem - ic * 9;              // ky*3+kx
    float v = (oc < COUTr) ? src[oc * CIN * 9 + ic * 9 + k] : 0.f;
    int chunks = CIN >> 4;
    int pairs  = COUTp >> 4;
    int chunk = ic >> 4, kin = ic & 15;
    int tg   = (kin >> 1) & 3;
    int slot = kin >> 3;
    int lane = (oc & 7) * 4 + tg;
    int blk  = (k * chunks + chunk) * pairs + (oc >> 4);
    int off_h = blk * 256 + lane * 8 + ((oc >> 3) & 1) * 4 + slot * 2 + (kin & 1);
    g_wpack[off + off_h] = __float2half(v);
}

// ---------------------------------------------------------------------------
// Scalar 3x3 conv (NCHW fp32 in), fused BN+relu.
// ---------------------------------------------------------------------------
template<int CIN, int COUT, int TX, int TY, int PX, int OCR, int ICB, bool NHWC_OUT>
__global__ void __launch_bounds__((TX / PX) * TY * (COUT / OCR))
conv3x3_k(const float* __restrict__ in, size_t inBS,
          const float* __restrict__ wg,
          const float* __restrict__ sc, const float* __restrict__ sh,
          void* __restrict__ out, size_t outBS) {
    constexpr int NGX  = TX / PX;
    constexpr int NOG  = COUT / OCR;
    constexpr int NTHR = NGX * TY * NOG;
    constexpr int SP   = TX + 3;

    __shared__ float sIn[ICB][TY + 2][SP];
    __shared__ float sW[ICB][COUT][12];

    const int tid = threadIdx.x;
    const int pxg = tid % NGX;
    const int tyl = (tid / NGX) % TY;
    const int ocg = tid / (NGX * TY);
    const int b   = blockIdx.z;
    const int tx0 = blockIdx.x * TX;
    const int ty0 = blockIdx.y * TY;

    const float* inB = in + (size_t)b * inBS;

    float acc[OCR][PX];
    #pragma unroll
    for (int o = 0; o < OCR; o++)
        #pragma unroll
        for (int p = 0; p < PX; p++) acc[o][p] = 0.f;

    for (int ic0 = 0; ic0 < CIN; ic0 += ICB) {
        __syncthreads();
        #pragma unroll 1
        for (int i = tid; i < ICB * (TY + 2) * (TX + 2); i += NTHR) {
            int ic = i / ((TY + 2) * (TX + 2));
            int r  = i - ic * ((TY + 2) * (TX + 2));
            int ry = r / (TX + 2);
            int rx = r - ry * (TX + 2);
            int gy = ty0 - 1 + ry;
            int gx = tx0 - 1 + rx;
            float v = 0.f;
            if ((unsigned)gy < (unsigned)Hh && (unsigned)gx < (unsigned)Ww)
                v = inB[(size_t)(ic0 + ic) * HWc + (size_t)gy * Ww + gx];
            sIn[ic][ry][rx] = v;
        }
        #pragma unroll 1
        for (int i = tid; i < ICB * COUT * 9; i += NTHR) {
            int ic = i / (COUT * 9);
            int r  = i - ic * (COUT * 9);
            int oc = r / 9;
            int k  = r - oc * 9;
            sW[ic][oc][k] = wg[((size_t)oc * CIN + ic0 + ic) * 9 + k];
        }
        __syncthreads();

        #pragma unroll 2
        for (int ic = 0; ic < ICB; ic++) {
            float r0[PX + 2], r1[PX + 2], r2[PX + 2];
            #pragma unroll
            for (int j = 0; j < PX + 2; j++) {
                r0[j] = sIn[ic][tyl + 0][pxg * PX + j];
                r1[j] = sIn[ic][tyl + 1][pxg * PX + j];
                r2[j] = sIn[ic][tyl + 2][pxg * PX + j];
            }
            #pragma unroll
            for (int o = 0; o < OCR; o++) {
                const float4 wa = *reinterpret_cast<const float4*>(&sW[ic][ocg * OCR + o][0]);
                const float4 wb = *reinterpret_cast<const float4*>(&sW[ic][ocg * OCR + o][4]);
                const float  wc = sW[ic][ocg * OCR + o][8];
                #pragma unroll
                for (int p = 0; p < PX; p++) {
                    float a = acc[o][p];
                    a = fmaf(r0[p    ], wa.x, a);
                    a = fmaf(r0[p + 1], wa.y, a);
                    a = fmaf(r0[p + 2], wa.z, a);
                    a = fmaf(r1[p    ], wa.w, a);
                    a = fmaf(r1[p + 1], wb.x, a);
                    a = fmaf(r1[p + 2], wb.y, a);
                    a = fmaf(r2[p    ], wb.z, a);
                    a = fmaf(r2[p + 1], wb.w, a);
                    a = fmaf(r2[p + 2], wc,   a);
                    acc[o][p] = a;
                }
            }
        }
    }

    const int y = ty0 + tyl;
    if (y < Hh) {
        #pragma unroll
        for (int o = 0; o < OCR; o++) {
            int oc = ocg * OCR + o;
            float scale = sc[oc], shift = sh[oc];
            #pragma unroll
            for (int p = 0; p < PX; p++) {
                int x = tx0 + pxg * PX + p;
                if (x < Ww) {
                    float v = fmaxf(fmaf(acc[o][p], scale, shift), 0.f);
                    if (NHWC_OUT) {
                        __half* outB = (__half*)out + (size_t)b * outBS;
                        outB[((size_t)y * Ww + x) * COUT + oc] = __float2half(v);
                    } else {
                        float* outB = (float*)out + (size_t)b * outBS;
                        outB[(size_t)oc * HWc + (size_t)y * Ww + x] = v;
                    }
                }
            }
        }
    }
}

template<int CIN, int COUT, int TX, int TY, int PX, int OCR, int ICB, bool NHWC_OUT>
static void run_conv(const float* in, size_t inBS,
                     const float* w, const float* s, const float* t,
                     void* out, size_t outBS) {
    dim3 grid((Ww + TX - 1) / TX, (Hh + TY - 1) / TY, Bc);
    dim3 block((TX / PX) * TY * (COUT / OCR));
    conv3x3_k<CIN, COUT, TX, TY, PX, OCR, ICB, NHWC_OUT><<<grid, block>>>(in, inBS, w, s, t, out, outBS);
}

// ---------------------------------------------------------------------------
// Warp-MMA fp16 3x3 conv, NHWC in, ldmatrix A + paired LDS.128 B.
//  CTA: 256 thr / 8 warps; warps 0..6: m16 px-tile x ROWS output rows.
//  OUTMODE: 0 = half NHWC, 1 = fp32 NCHW(NPL planes @ chbase), 2 = both.
// ---------------------------------------------------------------------------
template<int CHUNKS, int N8, int APH, int ROWS, int OUTMODE, bool IN_HALF, int COUTR, int NPL>
__global__ void __launch_bounds__(256, 2)
convmmh(const void* __restrict__ in,
        const __half* __restrict__ wpack,
        const float* __restrict__ sc, const float* __restrict__ sh,
        __half* __restrict__ o_nhwc,
        float* __restrict__ o_nchw, int chbase) {
    constexpr int CIN    = CHUNKS * 16;
    constexpr int COUT   = N8 * 8;
    constexpr int PAIRS  = N8 / 2;
    constexpr int APB    = APH * 2;             // bytes per staged px
    constexpr int SLAB_B = SLABPX * APB;
    constexpr int NSLAB  = ROWS + 2;
    constexpr int BKY_H  = 3 * CHUNKS * N8 * 128;  // halves per ky block
    constexpr int OPITCH = COUT + 2;
    constexpr int EPIPLN = XO * OPITCH * 4;

    extern __shared__ __align__(16) char smem[];
    char* smA = smem;
    char* smB = smem + NSLAB * SLAB_B;

    const int tid  = threadIdx.x;
    const int lane = tid & 31;
    const int wrp  = tid >> 5;
    const int mb   = wrp * 16;
    const int g    = lane >> 2;
    const int tg   = lane & 3;

    const int x0 = blockIdx.x * XO;
    const int y0 = blockIdx.y * ROWS;
    const int b  = blockIdx.z;

    // ---- stage A: NSLAB row-slabs (y0-1 ..) as half ----
    if (IN_HALF) {
        const __half* inB = (const __half*)in + (size_t)b * HWc * CIN;
        constexpr int LP = CIN / 8;             // uint4 (8 halves) per px
        #pragma unroll 4
        for (int i = tid; i < NSLAB * SLABPX * LP; i += 256) {
            int slab = i / (SLABPX * LP);
            int rem  = i - slab * (SLABPX * LP);
            int px   = rem / LP;
            int c8   = rem - px * LP;
            int gy = y0 - 1 + slab, gx = x0 - 1 + px;
            uint4 v = make_uint4(0, 0, 0, 0);
            if ((unsigned)gy < (unsigned)Hh && (unsigned)gx < (unsigned)Ww)
                v = *reinterpret_cast<const uint4*>(inB + ((size_t)gy * Ww + gx) * CIN + c8 * 8);
            *reinterpret_cast<uint4*>(smA + slab * SLAB_B + px * APB + c8 * 16) = v;
        }
    } else {
        const float* inB = (const float*)in + (size_t)b * HWc * CIN;
        constexpr int LP = CIN / 4;             // float4 per px
        #pragma unroll 4
        for (int i = tid; i < NSLAB * SLABPX * LP; i += 256) {
            int slab = i / (SLABPX * LP);
            int rem  = i - slab * (SLABPX * LP);
            int px   = rem / LP;
            int c4   = rem - px * LP;
            int gy = y0 - 1 + slab, gx = x0 - 1 + px;
            float4 v = make_float4(0.f, 0.f, 0.f, 0.f);
            if ((unsigned)gy < (unsigned)Hh && (unsigned)gx < (unsigned)Ww)
                v = *reinterpret_cast<const float4*>(inB + ((size_t)gy * Ww + gx) * CIN + c4 * 4);
            __half2 h0 = __floats2half2_rn(v.x, v.y);
            __half2 h1 = __floats2half2_rn(v.z, v.w);
            uint2 st = make_uint2(*reinterpret_cast<uint32_t*>(&h0),
                                  *reinterpret_cast<uint32_t*>(&h1));
            *reinterpret_cast<uint2*>(smA + slab * SLAB_B + px * APB + c4 * 8) = st;
        }
    }

    float acc[ROWS][N8][4];
    #pragma unroll
    for (int r = 0; r < ROWS; r++)
        #pragma unroll
        for (int n = 0; n < N8; n++)
            #pragma unroll
            for (int k = 0; k < 4; k++) acc[r][n][k] = 0.f;

    // ldmatrix per-lane address offset within a (slab, px-tile) base
    const uint32_t smA_sh = (uint32_t)__cvta_generic_to_shared(smA);
    const uint32_t smB_sh = (uint32_t)__cvta_generic_to_shared(smB);
    const uint32_t laneOff = (uint32_t)((lane & 15) * APB + ((lane & 16) ? 16 : 0));

    #pragma unroll 1
    for (int ky = 0; ky < 3; ky++) {
        __syncthreads();
        const uint4* wsrc = reinterpret_cast<const uint4*>(wpack + ky * BKY_H);
        #pragma unroll 2
        for (int i = tid; i < BKY_H / 8; i += 256)
            reinterpret_cast<uint4*>(smB)[i] = wsrc[i];
        __syncthreads();

        if (wrp < 7) {
            #pragma unroll
            for (int kx = 0; kx < 3; kx++) {
                const uint32_t abase = smA_sh + (uint32_t)(ky * SLAB_B + (mb + kx) * APB) + laneOff;
                #pragma unroll
                for (int chunk = 0; chunk < CHUNKS; chunk++) {
                    uint32_t a[ROWS][4];
                    #pragma unroll
                    for (int r = 0; r < ROWS; r++)
                        ldmA(a[r], abase + (uint32_t)(r * SLAB_B + chunk * 32));
                    const uint32_t bb = smB_sh +
                        (uint32_t)(((kx * CHUNKS + chunk) * PAIRS) * 512 + lane * 16);
                    #pragma unroll
                    for (int pr = 0; pr < PAIRS; pr++) {
                        uint4 bv;
                        asm volatile("ld.shared.v4.u32 {%0,%1,%2,%3}, [%4];"
                            : "=r"(bv.x), "=r"(bv.y), "=r"(bv.z), "=r"(bv.w)
                            : "r"(bb + (uint32_t)(pr * 512)));
                        #pragma unroll
                        for (int r = 0; r < ROWS; r++) {
                            mma16(acc[r][2 * pr],     a[r][0], a[r][1], a[r][2], a[r][3], bv.x, bv.y);
                            mma16(acc[r][2 * pr + 1], a[r][0], a[r][1], a[r][2], a[r][3], bv.z, bv.w);
                        }
                    }
                }
            }
        }
    }

    // ---- epilogue: regs -> smem fp32 [row][px][oc] ----
    __syncthreads();
    if (wrp < 7) {
        int pxb = mb + g;
        #pragma unroll
        for (int r = 0; r < ROWS; r++) {
            #pragma unroll
            for (int n = 0; n < N8; n++) {
                int oc = n * 8 + 2 * tg;
                *reinterpret_cast<float2*>(smem + r * EPIPLN + (pxb * OPITCH + oc) * 4) =
                    make_float2(acc[r][n][0], acc[r][n][1]);
                *reinterpret_cast<float2*>(smem + r * EPIPLN + ((pxb + 8) * OPITCH + oc) * 4) =
                    make_float2(acc[r][n][2], acc[r][n][3]);
            }
        }
    }
    __syncthreads();

    // ---- BN + relu + store ----
    if (OUTMODE == 0 || OUTMODE == 2) {
        __half* ob = o_nhwc + (size_t)b * HWc * COUT;
        #pragma unroll 1
        for (int i = tid; i < ROWS * XO * (COUT / 4); i += 256) {
            int rr  = i / (XO * (COUT / 4));
            int rem = i - rr * (XO * (COUT / 4));
            int px  = rem / (COUT / 4);
            int c4  = (rem - px * (COUT / 4)) * 4;
            if (x0 + px >= Ww || y0 + rr >= Hh) continue;
            const float* sp = reinterpret_cast<const float*>(
                smem + rr * EPIPLN + (px * OPITCH + c4) * 4);
            float4 s4 = *reinterpret_cast<const float4*>(sc + c4);
            float4 h4 = *reinterpret_cast<const float4*>(sh + c4);
            __half2 ha = __floats2half2_rn(fmaxf(fmaf(sp[0], s4.x, h4.x), 0.f),
                                           fmaxf(fmaf(sp[1], s4.y, h4.y), 0.f));
            __half2 hb = __floats2half2_rn(fmaxf(fmaf(sp[2], s4.z, h4.z), 0.f),
                                           fmaxf(fmaf(sp[3], s4.w, h4.w), 0.f));
            uint2 st = make_uint2(*reinterpret_cast<uint32_t*>(&ha),
                                  *reinterpret_cast<uint32_t*>(&hb));
            *reinterpret_cast<uint2*>(ob + ((size_t)(y0 + rr) * Ww + x0 + px) * COUT + c4) = st;
        }
    }
    if (OUTMODE == 1 || OUTMODE == 2) {
        #pragma unroll 1
        for (int i = tid; i < ROWS * COUTR * XO; i += 256) {
            int px = i % XO;
            int t2 = i / XO;
            int c  = t2 % COUTR;
            int rr = t2 / COUTR;
            if (x0 + px >= Ww || y0 + rr >= Hh) continue;
            float v = *reinterpret_cast<const float*>(
                smem + rr * EPIPLN + (px * OPITCH + c) * 4);
            float o = fmaxf(fmaf(v, sc[c], sh[c]), 0.f);
            o_nchw[((size_t)b * NPL + chbase + c) * HWc + (size_t)(y0 + rr) * Ww + x0 + px] = o;
        }
    }
}

template<int CHUNKS, int N8, int APH, int ROWS, int OUTMODE, bool IN_HALF, int COUTR, int NPL>
static void run_mmh(const void* in, int woff, const float* s, const float* t,
                    void* o_nhwc, float* o_nchw, int chbase) {
    constexpr int APB  = APH * 2;
    constexpr int MAIN = (ROWS + 2) * SLABPX * APB + 3 * CHUNKS * N8 * 256;
    constexpr int EPI  = ROWS * XO * (N8 * 8 + 2) * 4;
    constexpr int SM   = MAIN > EPI ? MAIN : EPI;
    __half* wp = nullptr;
    cudaGetSymbolAddress((void**)&wp, g_wpack);
    cudaFuncSetAttribute(convmmh<CHUNKS, N8, APH, ROWS, OUTMODE, IN_HALF, COUTR, NPL>,
                         cudaFuncAttributeMaxDynamicSharedMemorySize, SM);
    dim3 grid((Ww + XO - 1) / XO, (Hh + ROWS - 1) / ROWS, Bc);
    convmmh<CHUNKS, N8, APH, ROWS, OUTMODE, IN_HALF, COUTR, NPL><<<grid, 256, SM>>>(
        in, wp + woff, s, t, (__half*)o_nhwc, o_nchw, chbase);
}

// ---------------------------------------------------------------------------
extern "C" void kernel_launch(void* const* d_in, const int* in_sizes, int n_in,
                              void* d_out, int out_size) {
    const float* points = (const float*)d_in[0];
    const float* vfe_w  = (const float*)d_in[1];
    const float* vfe_s  = (const float*)d_in[2];
    const float* vfe_t  = (const float*)d_in[3];
    const float* b1_w0  = (const float*)d_in[4];
    const float* b1_s0  = (const float*)d_in[5];
    const float* b1_t0  = (const float*)d_in[6];
    const float* b1_w   = (const float*)d_in[7];
    const float* b1_s   = (const float*)d_in[8];
    const float* b1_t   = (const float*)d_in[9];
    const float* b2_w0  = (const float*)d_in[10];
    const float* b2_s0  = (const float*)d_in[11];
    const float* b2_t0  = (const float*)d_in[12];
    const float* b2_w   = (const float*)d_in[13];
    const float* b2_s   = (const float*)d_in[14];
    const float* b2_t   = (const float*)d_in[15];
    const float* b3_w0  = (const float*)d_in[16];
    const float* b3_s0  = (const float*)d_in[17];
    const float* b3_t0  = (const float*)d_in[18];
    const float* b3_w   = (const float*)d_in[19];
    const float* b3_s   = (const float*)d_in[20];
    const float* b3_t   = (const float*)d_in[21];
    float* out = (float*)d_out;

    const int npts = in_sizes[0] / 4;
    const int nper = npts / Bc;

    float *bufA = nullptr, *bufB = nullptr;
    cudaGetSymbolAddress((void**)&bufA, g_bufA);
    cudaGetSymbolAddress((void**)&bufB, g_bufB);

    const size_t HWs = (size_t)HWc;

    // Weight pre-pack + front-end
    PackArgs pa{b1_w0, b2_w, b3_w0, b3_w};
    pack_all<<<dim3(144, 12), 256>>>(pa);
    zero_kernel<<<4096, 256>>>();
    count_kernel<<<(npts + 255) / 256, 256>>>(points, npts, nper);
    vfe_kernel<<<(npts + 255) / 256, 256>>>(points, vfe_w, vfe_s, vfe_t, npts, nper);

    // Block 1: 64->4 mma (fp32 canvas -> 4-plane fp32 NCHW), then 3x scalar 4->4
    run_mmh<4, 2, 72, 2, 1, false, 4, 4>(bufA, WO_B1C0, b1_s0, b1_t0, nullptr, bufB, 0);
    run_conv< 4, 4, 32, 16, 2, 4, 4, false>(bufB, 4 * HWs, b1_w +   0, b1_s + 0, b1_t + 0, bufA, 4 * HWs);
    run_conv< 4, 4, 32, 16, 2, 4, 4, false>(bufA, 4 * HWs, b1_w + 144, b1_s + 4, b1_t + 4, bufB, 4 * HWs);
    run_conv< 4, 4, 32, 16, 2, 4, 4, false>(bufB, 4 * HWs, b1_w + 288, b1_s + 8, b1_t + 8, out,  84 * HWs);

    // Block 2: 4->16 scalar (NCHW fp32 -> NHWC half), then 5x 16->16 fp16 mma (6 rows/CTA)
    run_conv< 4, 16, 32, 8, 2, 8, 4, true>(out, 84 * HWs, b2_w0, b2_s0, b2_t0, bufA, 16 * HWs);
    run_mmh<1, 2, 24, 6, 0, true, 16, 84>(bufA, WO_B2 +    0, b2_s +  0, b2_t +  0, bufB, nullptr, 0);
    run_mmh<1, 2, 24, 6, 0, true, 16, 84>(bufB, WO_B2 + 2304, b2_s + 16, b2_t + 16, bufA, nullptr, 0);
    run_mmh<1, 2, 24, 6, 0, true, 16, 84>(bufA, WO_B2 + 4608, b2_s + 32, b2_t + 32, bufB, nullptr, 0);
    run_mmh<1, 2, 24, 6, 0, true, 16, 84>(bufB, WO_B2 + 6912, b2_s + 48, b2_t + 48, bufA, nullptr, 0);
    run_mmh<1, 2, 24, 6, 2, true, 16, 84>(bufA, WO_B2 + 9216, b2_s + 64, b2_t + 64, bufB, out, 4);

    // Block 3: 16->64 fp16 mma, then 5x 64->64; last -> out ch[20,84)
    run_mmh<1, 8, 24, 2, 0, true, 64, 84>(bufB, WO_B3C0, b3_s0, b3_t0, bufA, nullptr, 0);
    run_mmh<4, 8, 72, 2, 0, true, 64, 84>(bufA, WO_B3 +      0, b3_s +   0, b3_t +   0, bufB, nullptr, 0);
    run_mmh<4, 8, 72, 2, 0, true, 64, 84>(bufB, WO_B3 +  36864, b3_s +  64, b3_t +  64, bufA, nullptr, 0);
    run_mmh<4, 8, 72, 2, 0, true, 64, 84>(bufA, WO_B3 +  73728, b3_s + 128, b3_t + 128, bufB, nullptr, 0);
    run_mmh<4, 8, 72, 2, 0, true, 64, 84>(bufB, WO_B3 + 110592, b3_s + 192, b3_t + 192, bufA, nullptr, 0);
    run_mmh<4, 8, 72, 2, 1, true, 64, 84>(bufA, WO_B3 + 147456, b3_s + 256, b3_t + 256, nullptr, out, 20);
}